// round 2
// baseline (speedup 1.0000x reference)
#include <cuda_runtime.h>
#include <math.h>

#define D_MODEL   1024
#define NUM_HEADS 16
#define D_K       64
#define SEQ       2048
#define BATCH     2
#define M_TOK     (BATCH*SEQ)   // 4096

// ---------------- scratch (no allocation allowed) ----------------
__device__ float g_lin[3][(size_t)M_TOK * D_MODEL];                 // QKV linear outputs
__device__ float g_q[(size_t)BATCH * NUM_HEADS * SEQ * D_K];        // [b,h,s,dk] roped
__device__ float g_k[(size_t)BATCH * NUM_HEADS * SEQ * D_K];
__device__ float g_v[(size_t)BATCH * NUM_HEADS * SEQ * D_K];
__device__ float g_attn[(size_t)M_TOK * D_MODEL];                   // attention out [b,s,h*dk]

// ---------------- SGEMM: C[M,N] = A[M,K] * W[N,K]^T  (M=4096, N=K=1024) ----------------
// 128x128 tile, BK=8, 256 threads, 8x8 micro-tile (split 4+4).
__device__ __forceinline__ void sgemm_body(const float* __restrict__ A,
                                           const float* __restrict__ W,
                                           float* __restrict__ C)
{
    const int K = D_MODEL;
    const int N = D_MODEL;
    __shared__ float As[8][128];
    __shared__ float Bs[8][128];

    const int bm = blockIdx.y * 128;
    const int bn = blockIdx.x * 128;
    const int t  = threadIdx.x;
    const int tx = t & 15;
    const int ty = t >> 4;
    const int lr = t >> 1;          // 0..127 row within tile
    const int lc = (t & 1) * 4;     // k offset 0 or 4

    const float* Ap = A + (size_t)(bm + lr) * K + lc;
    const float* Wp = W + (size_t)(bn + lr) * K + lc;

    float acc[8][8];
#pragma unroll
    for (int i = 0; i < 8; i++)
#pragma unroll
        for (int j = 0; j < 8; j++) acc[i][j] = 0.f;

    for (int k0 = 0; k0 < K; k0 += 8) {
        float4 av = *(const float4*)(Ap + k0);
        float4 wv = *(const float4*)(Wp + k0);
        As[lc+0][lr] = av.x; As[lc+1][lr] = av.y; As[lc+2][lr] = av.z; As[lc+3][lr] = av.w;
        Bs[lc+0][lr] = wv.x; Bs[lc+1][lr] = wv.y; Bs[lc+2][lr] = wv.z; Bs[lc+3][lr] = wv.w;
        __syncthreads();
#pragma unroll
        for (int kk = 0; kk < 8; kk++) {
            float a[8], b[8];
            *(float4*)(a)     = *(const float4*)&As[kk][ty*4];
            *(float4*)(a + 4) = *(const float4*)&As[kk][64 + ty*4];
            *(float4*)(b)     = *(const float4*)&Bs[kk][tx*4];
            *(float4*)(b + 4) = *(const float4*)&Bs[kk][64 + tx*4];
#pragma unroll
            for (int i = 0; i < 8; i++)
#pragma unroll
                for (int j = 0; j < 8; j++)
                    acc[i][j] = fmaf(a[i], b[j], acc[i][j]);
        }
        __syncthreads();
    }

#pragma unroll
    for (int i = 0; i < 8; i++) {
        int r = bm + ((i < 4) ? (ty*4 + i) : (64 + ty*4 + (i - 4)));
        float4 v0 = make_float4(acc[i][0], acc[i][1], acc[i][2], acc[i][3]);
        float4 v1 = make_float4(acc[i][4], acc[i][5], acc[i][6], acc[i][7]);
        *(float4*)(C + (size_t)r * N + bn + tx*4)      = v0;
        *(float4*)(C + (size_t)r * N + bn + 64 + tx*4) = v1;
    }
}

__global__ void __launch_bounds__(256) qkv_gemm_kernel(const float* __restrict__ x,
                                                       const float* __restrict__ wq,
                                                       const float* __restrict__ wk,
                                                       const float* __restrict__ wv)
{
    const int z = blockIdx.z;
    const float* W = (z == 0) ? wq : (z == 1) ? wk : wv;
    sgemm_body(x, W, &g_lin[z][0]);
}

__global__ void __launch_bounds__(256) out_gemm_kernel(const float* __restrict__ wo,
                                                       float* __restrict__ out)
{
    sgemm_body(g_attn, wo, out);
}

// ---------------- RoPE + reshape to [b,h,s,dk] ----------------
__global__ void rope_kernel(const int* __restrict__ pos)
{
    const int z   = blockIdx.z;                         // 0=Q,1=K (rope), 2=V (copy)
    const int idx = blockIdx.x * blockDim.x + threadIdx.x;  // < 65536
    const int j     = idx & 31;
    const int h     = (idx >> 5) & 15;
    const int chunk = (idx >> 9) & 63;
    const int b     = (idx >> 15) & 1;

    const float* src_base = &g_lin[z][0] + ((size_t)b * SEQ) * D_MODEL + h * 64 + 2 * j;
    float* dst_base = ((z == 0) ? g_q : (z == 1) ? g_k : g_v)
                    + ((size_t)(b * NUM_HEADS + h) * SEQ) * D_K + 2 * j;
    const int s0 = chunk * 32;

    if (z == 2) {
        for (int ss = 0; ss < 32; ss++) {
            int s = s0 + ss;
            const float* sp = src_base + (size_t)s * D_MODEL;
            float* dp = dst_base + (size_t)s * D_K;
            dp[0] = sp[0]; dp[1] = sp[1];
        }
    } else {
        // freq = 10000^(-(2j)/64) = exp(-j * ln(10000)/32)
        const double freq   = exp((double)j * -0.28782313662425575);
        const double inv2pi = 0.15915494309189535;
        const double twopi  = 6.283185307179586;
        for (int ss = 0; ss < 32; ss++) {
            int s = s0 + ss;
            double ang = (double)pos[s] * freq;
            ang -= trunc(ang * inv2pi) * twopi;
            float c, sn;
            sincosf((float)ang, &sn, &c);
            const float* sp = src_base + (size_t)s * D_MODEL;
            float* dp = dst_base + (size_t)s * D_K;
            float x1 = sp[0], x2 = sp[1];
            dp[0] = x1 * c - x2 * sn;
            dp[1] = x1 * sn + x2 * c;
        }
    }
}

// ---------------- Flash attention (causal) ----------------
// Block: (q-tile of 64, head, batch). 256 threads, 4x4 micro-tiles.
// Writes g_attn via device symbol (NOT a host-passed pointer — that was the R1 bug).
#define FST 68
__global__ void __launch_bounds__(256) flash_kernel()
{
    extern __shared__ float sm[];
    float* Qt = sm;                 // [64][FST] (d-major)
    float* Kt = sm + 64 * FST;      // [64][FST] (d-major)
    float* Vs = sm + 2 * 64 * FST;  // [64][FST] (k-major: Vs[k][d])
    float* Pt = sm + 3 * 64 * FST;  // [64][FST] (k-major: Pt[k][q])

    const int qt = blockIdx.x;
    const int h  = blockIdx.y;
    const int b  = blockIdx.z;
    const int t  = threadIdx.x;
    const int tx = t & 15;
    const int ty = t >> 4;

    const size_t head_off = (size_t)(b * NUM_HEADS + h) * SEQ * D_K;
    const float* Qg = g_q + head_off;
    const float* Kg = g_k + head_off;
    const float* Vg = g_v + head_off;
    const int q0 = qt * 64;
    const float scale = 0.125f;  // 1/sqrt(64)

    // load Q tile transposed, pre-scaled
    for (int p = t; p < 1024; p += 256) {
        int row = p >> 4;
        int dc  = (p & 15) * 4;
        float4 v = *(const float4*)(Qg + (size_t)(q0 + row) * D_K + dc);
        Qt[(dc + 0) * FST + row] = v.x * scale;
        Qt[(dc + 1) * FST + row] = v.y * scale;
        Qt[(dc + 2) * FST + row] = v.z * scale;
        Qt[(dc + 3) * FST + row] = v.w * scale;
    }

    float m[4], l[4], o[4][4];
#pragma unroll
    for (int i = 0; i < 4; i++) {
        m[i] = -1e30f; l[i] = 0.f;
#pragma unroll
        for (int j = 0; j < 4; j++) o[i][j] = 0.f;
    }

    for (int kt = 0; kt <= qt; kt++) {
        __syncthreads();   // prior PV done / Q tile visible on first iteration
        // load K tile (transposed) and V tile (direct)
        for (int p = t; p < 1024; p += 256) {
            int row = p >> 4;
            int dc  = (p & 15) * 4;
            float4 kv = *(const float4*)(Kg + (size_t)(kt * 64 + row) * D_K + dc);
            Kt[(dc + 0) * FST + row] = kv.x;
            Kt[(dc + 1) * FST + row] = kv.y;
            Kt[(dc + 2) * FST + row] = kv.z;
            Kt[(dc + 3) * FST + row] = kv.w;
            float4 vv = *(const float4*)(Vg + (size_t)(kt * 64 + row) * D_K + dc);
            *(float4*)&Vs[row * FST + dc] = vv;
        }
        __syncthreads();

        // S = (Q*scale) K^T
        float s[4][4];
#pragma unroll
        for (int i = 0; i < 4; i++)
#pragma unroll
            for (int j = 0; j < 4; j++) s[i][j] = 0.f;
#pragma unroll 8
        for (int d = 0; d < 64; d++) {
            float a[4], bb[4];
            *(float4*)a  = *(const float4*)&Qt[d * FST + ty * 4];
            *(float4*)bb = *(const float4*)&Kt[d * FST + tx * 4];
#pragma unroll
            for (int i = 0; i < 4; i++)
#pragma unroll
                for (int j = 0; j < 4; j++)
                    s[i][j] = fmaf(a[i], bb[j], s[i][j]);
        }

        if (kt == qt) {  // diagonal tile: causal mask (local indices, q0 == k0)
#pragma unroll
            for (int i = 0; i < 4; i++)
#pragma unroll
                for (int j = 0; j < 4; j++)
                    if (tx * 4 + j > ty * 4 + i) s[i][j] = -1e30f;
        }

        // online softmax (row stats reduced over the 16 lanes with equal ty)
        float p_[4][4];
#pragma unroll
        for (int i = 0; i < 4; i++) {
            float mx = fmaxf(fmaxf(s[i][0], s[i][1]), fmaxf(s[i][2], s[i][3]));
#pragma unroll
            for (int off = 1; off < 16; off <<= 1)
                mx = fmaxf(mx, __shfl_xor_sync(0xffffffffu, mx, off));
            float mn = fmaxf(m[i], mx);
            float sf = __expf(m[i] - mn);
            m[i] = mn;
            float rs = 0.f;
#pragma unroll
            for (int j = 0; j < 4; j++) {
                p_[i][j] = __expf(s[i][j] - mn);
                rs += p_[i][j];
            }
#pragma unroll
            for (int off = 1; off < 16; off <<= 1)
                rs += __shfl_xor_sync(0xffffffffu, rs, off);
            l[i] = l[i] * sf + rs;
#pragma unroll
            for (int j = 0; j < 4; j++) o[i][j] *= sf;
        }

        // write P transposed: Pt[k][q]
#pragma unroll
        for (int i = 0; i < 4; i++)
#pragma unroll
            for (int j = 0; j < 4; j++)
                Pt[(tx * 4 + j) * FST + ty * 4 + i] = p_[i][j];
        __syncthreads();

        // O += P V
#pragma unroll 8
        for (int kk = 0; kk < 64; kk++) {
            float a[4], bb[4];
            *(float4*)a  = *(const float4*)&Pt[kk * FST + ty * 4];
            *(float4*)bb = *(const float4*)&Vs[kk * FST + tx * 4];
#pragma unroll
            for (int i = 0; i < 4; i++)
#pragma unroll
                for (int j = 0; j < 4; j++)
                    o[i][j] = fmaf(a[i], bb[j], o[i][j]);
        }
    }

    // epilogue: O / l, write to g_attn [b,s,h*dk] (device symbol)
#pragma unroll
    for (int i = 0; i < 4; i++) {
        float inv = 1.f / l[i];
        int q = q0 + ty * 4 + i;
        float4 v = make_float4(o[i][0] * inv, o[i][1] * inv, o[i][2] * inv, o[i][3] * inv);
        *(float4*)(g_attn + ((size_t)(b * SEQ) + q) * D_MODEL + h * 64 + tx * 4) = v;
    }
}

// ---------------- launch ----------------
extern "C" void kernel_launch(void* const* d_in, const int* in_sizes, int n_in,
                              void* d_out, int out_size)
{
    const float* x   = (const float*)d_in[0];
    const int*   pos = (const int*)  d_in[1];
    const float* wq  = (const float*)d_in[2];
    const float* wk  = (const float*)d_in[3];
    const float* wv  = (const float*)d_in[4];
    const float* wo  = (const float*)d_in[5];
    float* out = (float*)d_out;

    (void)in_sizes; (void)n_in; (void)out_size;

    const size_t flash_smem = 4u * 64u * FST * sizeof(float);  // 69632 B
    static bool attr_done = false;
    if (!attr_done) {
        cudaFuncSetAttribute(flash_kernel, cudaFuncAttributeMaxDynamicSharedMemorySize,
                             (int)flash_smem);
        attr_done = true;
    }

    // 1) QKV projections
    dim3 gemm_grid(D_MODEL / 128, M_TOK / 128, 3);
    qkv_gemm_kernel<<<gemm_grid, 256>>>(x, wq, wk, wv);

    // 2) RoPE + reshape
    rope_kernel<<<dim3(256, 1, 3), 256>>>(pos);

    // 3) flash attention
    flash_kernel<<<dim3(SEQ / 64, NUM_HEADS, BATCH), 256, flash_smem>>>();

    // 4) output projection
    out_gemm_kernel<<<dim3(D_MODEL / 128, M_TOK / 128, 1), 256>>>(wo, out);
}

// round 5
// speedup vs baseline: 1.4332x; 1.4332x over previous
#include <cuda_runtime.h>
#include <cuda_bf16.h>
#include <math.h>
#include <stdint.h>

#define D_MODEL   1024
#define NUM_HEADS 16
#define D_K       64
#define SEQ       2048
#define BATCH     2
#define M_TOK     (BATCH*SEQ)   // 4096

// ---------------- scratch (no allocation allowed) ----------------
__device__ float g_lin[3][(size_t)M_TOK * D_MODEL];                 // QKV linear outputs
__device__ float g_q[(size_t)BATCH * NUM_HEADS * SEQ * D_K];        // [b,h,s,dk] roped
__device__ float g_k[(size_t)BATCH * NUM_HEADS * SEQ * D_K];
__device__ float g_v[(size_t)BATCH * NUM_HEADS * SEQ * D_K];

// bf16-split operands
__device__ __nv_bfloat16 g_xhi[(size_t)M_TOK * D_MODEL];
__device__ __nv_bfloat16 g_xlo[(size_t)M_TOK * D_MODEL];
__device__ __nv_bfloat16 g_whi[4][(size_t)D_MODEL * D_MODEL];
__device__ __nv_bfloat16 g_wlo[4][(size_t)D_MODEL * D_MODEL];
__device__ __nv_bfloat16 g_ahi[(size_t)M_TOK * D_MODEL];            // attn out hi (bf16 split)
__device__ __nv_bfloat16 g_alo[(size_t)M_TOK * D_MODEL];            // attn out lo

// ---------------- helpers ----------------
__device__ __forceinline__ uint32_t smem_u32(const void* p) {
    uint32_t a;
    asm("{ .reg .u64 t; cvta.to.shared.u64 t, %1; cvt.u32.u64 %0, t; }" : "=r"(a) : "l"(p));
    return a;
}

__device__ __forceinline__ void ldmx4(uint32_t* r, uint32_t addr) {
    asm volatile("ldmatrix.sync.aligned.m8n8.x4.shared.b16 {%0,%1,%2,%3}, [%4];"
                 : "=r"(r[0]), "=r"(r[1]), "=r"(r[2]), "=r"(r[3]) : "r"(addr));
}

__device__ __forceinline__ void mma_bf16(float* d, const uint32_t* a, const uint32_t* b) {
    asm volatile("mma.sync.aligned.m16n8k16.row.col.f32.bf16.bf16.f32 "
                 "{%0,%1,%2,%3}, {%4,%5,%6,%7}, {%8,%9}, {%0,%1,%2,%3};"
                 : "+f"(d[0]), "+f"(d[1]), "+f"(d[2]), "+f"(d[3])
                 : "r"(a[0]), "r"(a[1]), "r"(a[2]), "r"(a[3]), "r"(b[0]), "r"(b[1]));
}

// ---------------- split conversion: fp32 -> (bf16 hi, bf16 lo) ----------------
__global__ void cvt_split_kernel(const float4* __restrict__ src,
                                 __nv_bfloat16* __restrict__ hi,
                                 __nv_bfloat16* __restrict__ lo, int n4)
{
    int i = blockIdx.x * blockDim.x + threadIdx.x;
    if (i >= n4) return;
    float4 v = src[i];
    __nv_bfloat16 h[4], l[4];
    float f[4] = {v.x, v.y, v.z, v.w};
#pragma unroll
    for (int j = 0; j < 4; j++) {
        h[j] = __float2bfloat16(f[j]);
        l[j] = __float2bfloat16(f[j] - __bfloat162float(h[j]));
    }
    *(uint2*)&hi[(size_t)i * 4] = *(uint2*)h;
    *(uint2*)&lo[(size_t)i * 4] = *(uint2*)l;
}

// ---------------- HMMA GEMM: C[M,N] = A[M,K] * W[N,K]^T (bf16 split, 3 MMAs) ----------
// 128x128 tile, BK=64, 8 warps as 2(M)x4(N), warp tile 64x32.
// smem: 4 tiles of [128 rows][64 bf16] = 128B rows, XOR-swizzled, 16KB each, 64KB total.
#define GEMM_SMEM (4 * 128 * 64 * 2)

__device__ __forceinline__ void mma_gemm_body(const __nv_bfloat16* __restrict__ Ahi,
                                              const __nv_bfloat16* __restrict__ Alo,
                                              const __nv_bfloat16* __restrict__ Whi,
                                              const __nv_bfloat16* __restrict__ Wlo,
                                              float* __restrict__ C)
{
    extern __shared__ char smem[];
    const uint32_t sb = smem_u32(smem);
    const int K = D_MODEL, N = D_MODEL;
    const int bm = blockIdx.y * 128;
    const int bn = blockIdx.x * 128;
    const int tid  = threadIdx.x;
    const int wid  = tid >> 5;
    const int lane = tid & 31;
    const int wm = (wid >> 2) * 64;   // warp M offset in tile
    const int wn = (wid & 3) * 32;    // warp N offset in tile

    const __nv_bfloat16* srcs[4] = {
        Ahi + (size_t)bm * K, Alo + (size_t)bm * K,
        Whi + (size_t)bn * K, Wlo + (size_t)bn * K };

    float acc[4][4][4];
#pragma unroll
    for (int i = 0; i < 4; i++)
#pragma unroll
        for (int j = 0; j < 4; j++)
#pragma unroll
            for (int e = 0; e < 4; e++) acc[i][j][e] = 0.f;

    const int rA = (lane & 7) + ((lane >> 3) & 1) * 8;  // row within 16-row frag
    const int pA = (lane >> 4) & 1;                     // k8 half select

    for (int c = 0; c < 16; ++c) {
        const int k0 = c * 64;
        __syncthreads();
#pragma unroll
        for (int t = 0; t < 4; t++) {
            const __nv_bfloat16* S = srcs[t];
#pragma unroll
            for (int i = tid; i < 1024; i += 256) {
                int row = i >> 3, slot = i & 7;
                uint4 v = *(const uint4*)(S + (size_t)row * K + k0 + slot * 8);
                *(uint4*)(smem + t * 16384 + row * 128 + (((slot ^ (row & 7)) << 4))) = v;
            }
        }
        __syncthreads();

#pragma unroll
        for (int kk = 0; kk < 4; kk++) {
            const int slot = kk * 2 + pA;
            uint32_t ah[4][4], al[4][4], bh[4][2], bl[4][2];
#pragma unroll
            for (int im = 0; im < 4; im++) {
                int row = wm + im * 16 + rA;
                uint32_t ad = sb + row * 128 + ((slot ^ (row & 7)) << 4);
                ldmx4(ah[im], ad);
                ldmx4(al[im], ad + 16384);
            }
#pragma unroll
            for (int g = 0; g < 2; g++) {
                int row = wn + g * 16 + rA;
                uint32_t bd = sb + 32768 + row * 128 + ((slot ^ (row & 7)) << 4);
                uint32_t t0[4], t1[4];
                ldmx4(t0, bd);
                ldmx4(t1, bd + 16384);
                bh[g * 2 + 0][0] = t0[0]; bh[g * 2 + 0][1] = t0[2];
                bh[g * 2 + 1][0] = t0[1]; bh[g * 2 + 1][1] = t0[3];
                bl[g * 2 + 0][0] = t1[0]; bl[g * 2 + 0][1] = t1[2];
                bl[g * 2 + 1][0] = t1[1]; bl[g * 2 + 1][1] = t1[3];
            }
#pragma unroll
            for (int im = 0; im < 4; im++)
#pragma unroll
                for (int jn = 0; jn < 4; jn++) {
                    mma_bf16(acc[im][jn], ah[im], bh[jn]);
                    mma_bf16(acc[im][jn], ah[im], bl[jn]);
                    mma_bf16(acc[im][jn], al[im], bh[jn]);
                }
        }
    }

    const int r0 = bm + wm + (lane >> 2);
    const int c0 = bn + wn + (lane & 3) * 2;
#pragma unroll
    for (int im = 0; im < 4; im++)
#pragma unroll
        for (int jn = 0; jn < 4; jn++) {
            float* p0 = C + (size_t)(r0 + im * 16) * N + c0 + jn * 8;
            float* p1 = C + (size_t)(r0 + im * 16 + 8) * N + c0 + jn * 8;
            *(float2*)p0 = make_float2(acc[im][jn][0], acc[im][jn][1]);
            *(float2*)p1 = make_float2(acc[im][jn][2], acc[im][jn][3]);
        }
}

__global__ void __launch_bounds__(256) qkv_mma_kernel()
{
    const int z = blockIdx.z;
    mma_gemm_body(g_xhi, g_xlo, &g_whi[z][0], &g_wlo[z][0], &g_lin[z][0]);
}

__global__ void __launch_bounds__(256) out_mma_kernel(float* __restrict__ out)
{
    mma_gemm_body(g_ahi, g_alo, &g_whi[3][0], &g_wlo[3][0], out);
}

// ---------------- RoPE + reshape to [b,h,s,dk] ----------------
__global__ void rope_kernel(const int* __restrict__ pos)
{
    const int z   = blockIdx.z;                         // 0=Q,1=K (rope), 2=V (copy)
    const int idx = blockIdx.x * blockDim.x + threadIdx.x;  // < 65536
    const int j     = idx & 31;
    const int h     = (idx >> 5) & 15;
    const int chunk = (idx >> 9) & 63;
    const int b     = (idx >> 15) & 1;

    const float* src_base = &g_lin[z][0] + ((size_t)b * SEQ) * D_MODEL + h * 64 + 2 * j;
    float* dst_base = ((z == 0) ? g_q : (z == 1) ? g_k : g_v)
                    + ((size_t)(b * NUM_HEADS + h) * SEQ) * D_K + 2 * j;
    const int s0 = chunk * 32;

    if (z == 2) {
        for (int ss = 0; ss < 32; ss++) {
            int s = s0 + ss;
            const float* sp = src_base + (size_t)s * D_MODEL;
            float* dp = dst_base + (size_t)s * D_K;
            dp[0] = sp[0]; dp[1] = sp[1];
        }
    } else {
        const double freq   = exp((double)j * -0.28782313662425575);
        const double inv2pi = 0.15915494309189535;
        const double twopi  = 6.283185307179586;
        for (int ss = 0; ss < 32; ss++) {
            int s = s0 + ss;
            double ang = (double)pos[s] * freq;
            ang -= trunc(ang * inv2pi) * twopi;
            float c, sn;
            sincosf((float)ang, &sn, &c);
            const float* sp = src_base + (size_t)s * D_MODEL;
            float* dp = dst_base + (size_t)s * D_K;
            float x1 = sp[0], x2 = sp[1];
            dp[0] = x1 * c - x2 * sn;
            dp[1] = x1 * sn + x2 * c;
        }
    }
}

// ---------------- Flash attention (causal, fp32) ----------------
// Epilogue writes bf16 hi/lo split directly to g_ahi/g_alo (device symbols).
#define FST 68
__global__ void __launch_bounds__(256) flash_kernel()
{
    extern __shared__ float sm[];
    float* Qt = sm;                 // [64][FST] (d-major)
    float* Kt = sm + 64 * FST;      // [64][FST] (d-major)
    float* Vs = sm + 2 * 64 * FST;  // [64][FST] (k-major: Vs[k][d])
    float* Pt = sm + 3 * 64 * FST;  // [64][FST] (k-major: Pt[k][q])

    const int qt = blockIdx.x;
    const int h  = blockIdx.y;
    const int b  = blockIdx.z;
    const int t  = threadIdx.x;
    const int tx = t & 15;
    const int ty = t >> 4;

    const size_t head_off = (size_t)(b * NUM_HEADS + h) * SEQ * D_K;
    const float* Qg = g_q + head_off;
    const float* Kg = g_k + head_off;
    const float* Vg = g_v + head_off;
    const int q0 = qt * 64;
    const float scale = 0.125f;

    for (int p = t; p < 1024; p += 256) {
        int row = p >> 4;
        int dc  = (p & 15) * 4;
        float4 v = *(const float4*)(Qg + (size_t)(q0 + row) * D_K + dc);
        Qt[(dc + 0) * FST + row] = v.x * scale;
        Qt[(dc + 1) * FST + row] = v.y * scale;
        Qt[(dc + 2) * FST + row] = v.z * scale;
        Qt[(dc + 3) * FST + row] = v.w * scale;
    }

    float m[4], l[4], o[4][4];
#pragma unroll
    for (int i = 0; i < 4; i++) {
        m[i] = -1e30f; l[i] = 0.f;
#pragma unroll
        for (int j = 0; j < 4; j++) o[i][j] = 0.f;
    }

    for (int kt = 0; kt <= qt; kt++) {
        __syncthreads();
        for (int p = t; p < 1024; p += 256) {
            int row = p >> 4;
            int dc  = (p & 15) * 4;
            float4 kv = *(const float4*)(Kg + (size_t)(kt * 64 + row) * D_K + dc);
            Kt[(dc + 0) * FST + row] = kv.x;
            Kt[(dc + 1) * FST + row] = kv.y;
            Kt[(dc + 2) * FST + row] = kv.z;
            Kt[(dc + 3) * FST + row] = kv.w;
            float4 vv = *(const float4*)(Vg + (size_t)(kt * 64 + row) * D_K + dc);
            *(float4*)&Vs[row * FST + dc] = vv;
        }
        __syncthreads();

        float s[4][4];
#pragma unroll
        for (int i = 0; i < 4; i++)
#pragma unroll
            for (int j = 0; j < 4; j++) s[i][j] = 0.f;
#pragma unroll 8
        for (int d = 0; d < 64; d++) {
            float a[4], bb[4];
            *(float4*)a  = *(const float4*)&Qt[d * FST + ty * 4];
            *(float4*)bb = *(const float4*)&Kt[d * FST + tx * 4];
#pragma unroll
            for (int i = 0; i < 4; i++)
#pragma unroll
                for (int j = 0; j < 4; j++)
                    s[i][j] = fmaf(a[i], bb[j], s[i][j]);
        }

        if (kt == qt) {
#pragma unroll
            for (int i = 0; i < 4; i++)
#pragma unroll
                for (int j = 0; j < 4; j++)
                    if (tx * 4 + j > ty * 4 + i) s[i][j] = -1e30f;
        }

        float p_[4][4];
#pragma unroll
        for (int i = 0; i < 4; i++) {
            float mx = fmaxf(fmaxf(s[i][0], s[i][1]), fmaxf(s[i][2], s[i][3]));
#pragma unroll
            for (int off = 1; off < 16; off <<= 1)
                mx = fmaxf(mx, __shfl_xor_sync(0xffffffffu, mx, off));
            float mn = fmaxf(m[i], mx);
            float sf = __expf(m[i] - mn);
            m[i] = mn;
            float rs = 0.f;
#pragma unroll
            for (int j = 0; j < 4; j++) {
                p_[i][j] = __expf(s[i][j] - mn);
                rs += p_[i][j];
            }
#pragma unroll
            for (int off = 1; off < 16; off <<= 1)
                rs += __shfl_xor_sync(0xffffffffu, rs, off);
            l[i] = l[i] * sf + rs;
#pragma unroll
            for (int j = 0; j < 4; j++) o[i][j] *= sf;
        }

#pragma unroll
        for (int i = 0; i < 4; i++)
#pragma unroll
            for (int j = 0; j < 4; j++)
                Pt[(tx * 4 + j) * FST + ty * 4 + i] = p_[i][j];
        __syncthreads();

#pragma unroll 8
        for (int kk = 0; kk < 64; kk++) {
            float a[4], bb[4];
            *(float4*)a  = *(const float4*)&Pt[kk * FST + ty * 4];
            *(float4*)bb = *(const float4*)&Vs[kk * FST + tx * 4];
#pragma unroll
            for (int i = 0; i < 4; i++)
#pragma unroll
                for (int j = 0; j < 4; j++)
                    o[i][j] = fmaf(a[i], bb[j], o[i][j]);
        }
    }

    // epilogue: O / l, split to bf16 hi/lo, write to g_ahi/g_alo [b,s,h*dk]
#pragma unroll
    for (int i = 0; i < 4; i++) {
        float inv = 1.f / l[i];
        int q = q0 + ty * 4 + i;
        size_t base = ((size_t)(b * SEQ) + q) * D_MODEL + h * 64 + tx * 4;
        __nv_bfloat16 hh[4], ll[4];
#pragma unroll
        for (int j = 0; j < 4; j++) {
            float v = o[i][j] * inv;
            hh[j] = __float2bfloat16(v);
            ll[j] = __float2bfloat16(v - __bfloat162float(hh[j]));
        }
        *(uint2*)(g_ahi + base) = *(uint2*)hh;
        *(uint2*)(g_alo + base) = *(uint2*)ll;
    }
}

// ---------------- launch ----------------
extern "C" void kernel_launch(void* const* d_in, const int* in_sizes, int n_in,
                              void* d_out, int out_size)
{
    const float* x   = (const float*)d_in[0];
    const int*   pos = (const int*)  d_in[1];
    const float* wq  = (const float*)d_in[2];
    const float* wk  = (const float*)d_in[3];
    const float* wv  = (const float*)d_in[4];
    const float* wo  = (const float*)d_in[5];
    float* out = (float*)d_out;

    (void)in_sizes; (void)n_in; (void)out_size;

    const size_t flash_smem = 4u * 64u * FST * sizeof(float);  // 69632 B
    static bool attr_done = false;
    if (!attr_done) {
        cudaFuncSetAttribute(flash_kernel, cudaFuncAttributeMaxDynamicSharedMemorySize,
                             (int)flash_smem);
        cudaFuncSetAttribute(qkv_mma_kernel, cudaFuncAttributeMaxDynamicSharedMemorySize,
                             GEMM_SMEM);
        cudaFuncSetAttribute(out_mma_kernel, cudaFuncAttributeMaxDynamicSharedMemorySize,
                             GEMM_SMEM);
        attr_done = true;
    }

    __nv_bfloat16 *xhi, *xlo, *whi0, *wlo0;
    cudaGetSymbolAddress((void**)&xhi,  g_xhi);
    cudaGetSymbolAddress((void**)&xlo,  g_xlo);
    cudaGetSymbolAddress((void**)&whi0, g_whi);
    cudaGetSymbolAddress((void**)&wlo0, g_wlo);

    const int n4x = M_TOK * D_MODEL / 4;       // 1M
    const int n4w = D_MODEL * D_MODEL / 4;     // 256K
    const size_t wsz = (size_t)D_MODEL * D_MODEL;

    // 0) conversions (all srcs are harness device pointers — safe in host code)
    cvt_split_kernel<<<(n4x + 255) / 256, 256>>>((const float4*)x, xhi, xlo, n4x);
    cvt_split_kernel<<<(n4w + 255) / 256, 256>>>((const float4*)wq, whi0, wlo0, n4w);
    cvt_split_kernel<<<(n4w + 255) / 256, 256>>>((const float4*)wk, whi0 + wsz, wlo0 + wsz, n4w);
    cvt_split_kernel<<<(n4w + 255) / 256, 256>>>((const float4*)wv, whi0 + 2 * wsz, wlo0 + 2 * wsz, n4w);
    cvt_split_kernel<<<(n4w + 255) / 256, 256>>>((const float4*)wo, whi0 + 3 * wsz, wlo0 + 3 * wsz, n4w);

    // 1) QKV projections (HMMA bf16 split)
    qkv_mma_kernel<<<dim3(D_MODEL / 128, M_TOK / 128, 3), 256, GEMM_SMEM>>>();

    // 2) RoPE + reshape
    rope_kernel<<<dim3(256, 1, 3), 256>>>(pos);

    // 3) flash attention (fp32; writes bf16 split directly)
    flash_kernel<<<dim3(SEQ / 64, NUM_HEADS, BATCH), 256, flash_smem>>>();

    // 4) output projection (HMMA)
    out_mma_kernel<<<dim3(D_MODEL / 128, M_TOK / 128, 1), 256, GEMM_SMEM>>>(out);
}

// round 6
// speedup vs baseline: 2.3831x; 1.6628x over previous
#include <cuda_runtime.h>
#include <cuda_bf16.h>
#include <math.h>
#include <stdint.h>

#define D_MODEL   1024
#define NUM_HEADS 16
#define D_K       64
#define SEQ       2048
#define BATCH     2
#define M_TOK     (BATCH*SEQ)   // 4096

// ---------------- scratch (no allocation allowed) ----------------
__device__ float g_lin[3][(size_t)M_TOK * D_MODEL];                 // QKV linear outputs (fp32)

// bf16-split operands
__device__ __nv_bfloat16 g_xhi[(size_t)M_TOK * D_MODEL];
__device__ __nv_bfloat16 g_xlo[(size_t)M_TOK * D_MODEL];
__device__ __nv_bfloat16 g_whi[4][(size_t)D_MODEL * D_MODEL];
__device__ __nv_bfloat16 g_wlo[4][(size_t)D_MODEL * D_MODEL];
__device__ __nv_bfloat16 g_ahi[(size_t)M_TOK * D_MODEL];            // attn out hi
__device__ __nv_bfloat16 g_alo[(size_t)M_TOK * D_MODEL];            // attn out lo

// roped Q/K and V, bf16 hi/lo, [b,h,s,dk]
#define HSZ ((size_t)BATCH * NUM_HEADS * SEQ * D_K)
__device__ __nv_bfloat16 g_qhi[HSZ], g_qlo[HSZ];
__device__ __nv_bfloat16 g_khi[HSZ], g_klo[HSZ];
__device__ __nv_bfloat16 g_vhi[HSZ], g_vlo[HSZ];

// ---------------- helpers ----------------
__device__ __forceinline__ uint32_t smem_u32(const void* p) {
    uint32_t a;
    asm("{ .reg .u64 t; cvta.to.shared.u64 t, %1; cvt.u32.u64 %0, t; }" : "=r"(a) : "l"(p));
    return a;
}

__device__ __forceinline__ void ldmx4(uint32_t* r, uint32_t addr) {
    asm volatile("ldmatrix.sync.aligned.m8n8.x4.shared.b16 {%0,%1,%2,%3}, [%4];"
                 : "=r"(r[0]), "=r"(r[1]), "=r"(r[2]), "=r"(r[3]) : "r"(addr));
}

__device__ __forceinline__ void ldmx4t(uint32_t* r, uint32_t addr) {
    asm volatile("ldmatrix.sync.aligned.m8n8.x4.trans.shared.b16 {%0,%1,%2,%3}, [%4];"
                 : "=r"(r[0]), "=r"(r[1]), "=r"(r[2]), "=r"(r[3]) : "r"(addr));
}

__device__ __forceinline__ void mma_bf16(float* d, const uint32_t* a, const uint32_t* b) {
    asm volatile("mma.sync.aligned.m16n8k16.row.col.f32.bf16.bf16.f32 "
                 "{%0,%1,%2,%3}, {%4,%5,%6,%7}, {%8,%9}, {%0,%1,%2,%3};"
                 : "+f"(d[0]), "+f"(d[1]), "+f"(d[2]), "+f"(d[3])
                 : "r"(a[0]), "r"(a[1]), "r"(a[2]), "r"(a[3]), "r"(b[0]), "r"(b[1]));
}

// pack two floats into bf16x2 hi + residual lo
__device__ __forceinline__ void split2(float a, float b, uint32_t& hi, uint32_t& lo) {
    __nv_bfloat162 h = __floats2bfloat162_rn(a, b);
    float ra = a - __bfloat162float(h.x);
    float rb = b - __bfloat162float(h.y);
    __nv_bfloat162 l = __floats2bfloat162_rn(ra, rb);
    hi = *(uint32_t*)&h;
    lo = *(uint32_t*)&l;
}

// ---------------- split conversion: fp32 -> (bf16 hi, bf16 lo) ----------------
__global__ void cvt_split_kernel(const float4* __restrict__ src,
                                 __nv_bfloat16* __restrict__ hi,
                                 __nv_bfloat16* __restrict__ lo, int n4)
{
    int i = blockIdx.x * blockDim.x + threadIdx.x;
    if (i >= n4) return;
    float4 v = src[i];
    __nv_bfloat16 h[4], l[4];
    float f[4] = {v.x, v.y, v.z, v.w};
#pragma unroll
    for (int j = 0; j < 4; j++) {
        h[j] = __float2bfloat16(f[j]);
        l[j] = __float2bfloat16(f[j] - __bfloat162float(h[j]));
    }
    *(uint2*)&hi[(size_t)i * 4] = *(uint2*)h;
    *(uint2*)&lo[(size_t)i * 4] = *(uint2*)l;
}

// ---------------- HMMA GEMM (proven R5): C[M,N] = A[M,K] * W[N,K]^T ----------------
#define GEMM_SMEM (4 * 128 * 64 * 2)

__device__ __forceinline__ void mma_gemm_body(const __nv_bfloat16* __restrict__ Ahi,
                                              const __nv_bfloat16* __restrict__ Alo,
                                              const __nv_bfloat16* __restrict__ Whi,
                                              const __nv_bfloat16* __restrict__ Wlo,
                                              float* __restrict__ C)
{
    extern __shared__ char smem[];
    const uint32_t sb = smem_u32(smem);
    const int K = D_MODEL, N = D_MODEL;
    const int bm = blockIdx.y * 128;
    const int bn = blockIdx.x * 128;
    const int tid  = threadIdx.x;
    const int wid  = tid >> 5;
    const int lane = tid & 31;
    const int wm = (wid >> 2) * 64;
    const int wn = (wid & 3) * 32;

    const __nv_bfloat16* srcs[4] = {
        Ahi + (size_t)bm * K, Alo + (size_t)bm * K,
        Whi + (size_t)bn * K, Wlo + (size_t)bn * K };

    float acc[4][4][4];
#pragma unroll
    for (int i = 0; i < 4; i++)
#pragma unroll
        for (int j = 0; j < 4; j++)
#pragma unroll
            for (int e = 0; e < 4; e++) acc[i][j][e] = 0.f;

    const int rA = (lane & 7) + ((lane >> 3) & 1) * 8;
    const int pA = (lane >> 4) & 1;

    for (int c = 0; c < 16; ++c) {
        const int k0 = c * 64;
        __syncthreads();
#pragma unroll
        for (int t = 0; t < 4; t++) {
            const __nv_bfloat16* S = srcs[t];
#pragma unroll
            for (int i = tid; i < 1024; i += 256) {
                int row = i >> 3, slot = i & 7;
                uint4 v = *(const uint4*)(S + (size_t)row * K + k0 + slot * 8);
                *(uint4*)(smem + t * 16384 + row * 128 + (((slot ^ (row & 7)) << 4))) = v;
            }
        }
        __syncthreads();

#pragma unroll
        for (int kk = 0; kk < 4; kk++) {
            const int slot = kk * 2 + pA;
            uint32_t ah[4][4], al[4][4], bh[4][2], bl[4][2];
#pragma unroll
            for (int im = 0; im < 4; im++) {
                int row = wm + im * 16 + rA;
                uint32_t ad = sb + row * 128 + ((slot ^ (row & 7)) << 4);
                ldmx4(ah[im], ad);
                ldmx4(al[im], ad + 16384);
            }
#pragma unroll
            for (int g = 0; g < 2; g++) {
                int row = wn + g * 16 + rA;
                uint32_t bd = sb + 32768 + row * 128 + ((slot ^ (row & 7)) << 4);
                uint32_t t0[4], t1[4];
                ldmx4(t0, bd);
                ldmx4(t1, bd + 16384);
                bh[g * 2 + 0][0] = t0[0]; bh[g * 2 + 0][1] = t0[2];
                bh[g * 2 + 1][0] = t0[1]; bh[g * 2 + 1][1] = t0[3];
                bl[g * 2 + 0][0] = t1[0]; bl[g * 2 + 0][1] = t1[2];
                bl[g * 2 + 1][0] = t1[1]; bl[g * 2 + 1][1] = t1[3];
            }
#pragma unroll
            for (int im = 0; im < 4; im++)
#pragma unroll
                for (int jn = 0; jn < 4; jn++) {
                    mma_bf16(acc[im][jn], ah[im], bh[jn]);
                    mma_bf16(acc[im][jn], ah[im], bl[jn]);
                    mma_bf16(acc[im][jn], al[im], bh[jn]);
                }
        }
    }

    const int r0 = bm + wm + (lane >> 2);
    const int c0 = bn + wn + (lane & 3) * 2;
#pragma unroll
    for (int im = 0; im < 4; im++)
#pragma unroll
        for (int jn = 0; jn < 4; jn++) {
            float* p0 = C + (size_t)(r0 + im * 16) * N + c0 + jn * 8;
            float* p1 = C + (size_t)(r0 + im * 16 + 8) * N + c0 + jn * 8;
            *(float2*)p0 = make_float2(acc[im][jn][0], acc[im][jn][1]);
            *(float2*)p1 = make_float2(acc[im][jn][2], acc[im][jn][3]);
        }
}

__global__ void __launch_bounds__(256) qkv_mma_kernel()
{
    const int z = blockIdx.z;
    mma_gemm_body(g_xhi, g_xlo, &g_whi[z][0], &g_wlo[z][0], &g_lin[z][0]);
}

__global__ void __launch_bounds__(256) out_mma_kernel(float* __restrict__ out)
{
    mma_gemm_body(g_ahi, g_alo, &g_whi[3][0], &g_wlo[3][0], out);
}

// ---------------- RoPE + reshape to [b,h,s,dk], bf16 hi/lo output ----------------
__global__ void rope_kernel(const int* __restrict__ pos)
{
    const int z   = blockIdx.z;                         // 0=Q (rope+scale), 1=K (rope), 2=V (copy)
    const int idx = blockIdx.x * blockDim.x + threadIdx.x;
    const int j     = idx & 31;
    const int h     = (idx >> 5) & 15;
    const int chunk = (idx >> 9) & 63;
    const int b     = (idx >> 15) & 1;

    const float* src_base = &g_lin[z][0] + ((size_t)b * SEQ) * D_MODEL + h * 64 + 2 * j;
    __nv_bfloat16* dhi = (z == 0) ? g_qhi : (z == 1) ? g_khi : g_vhi;
    __nv_bfloat16* dlo = (z == 0) ? g_qlo : (z == 1) ? g_klo : g_vlo;
    const size_t dst_off = ((size_t)(b * NUM_HEADS + h) * SEQ) * D_K + 2 * j;
    const int s0 = chunk * 32;

    if (z == 2) {
        for (int ss = 0; ss < 32; ss++) {
            int s = s0 + ss;
            const float* sp = src_base + (size_t)s * D_MODEL;
            uint32_t hi, lo;
            split2(sp[0], sp[1], hi, lo);
            size_t o = dst_off + (size_t)s * D_K;
            *(uint32_t*)(dhi + o) = hi;
            *(uint32_t*)(dlo + o) = lo;
        }
    } else {
        const double freq   = exp((double)j * -0.28782313662425575);
        const double inv2pi = 0.15915494309189535;
        const double twopi  = 6.283185307179586;
        const float qscale = (z == 0) ? 0.125f : 1.0f;  // 1/sqrt(64), exact pow2
        for (int ss = 0; ss < 32; ss++) {
            int s = s0 + ss;
            double ang = (double)pos[s] * freq;
            ang -= trunc(ang * inv2pi) * twopi;
            float c, sn;
            sincosf((float)ang, &sn, &c);
            const float* sp = src_base + (size_t)s * D_MODEL;
            float x1 = sp[0], x2 = sp[1];
            float r1 = (x1 * c - x2 * sn) * qscale;
            float r2 = (x1 * sn + x2 * c) * qscale;
            uint32_t hi, lo;
            split2(r1, r2, hi, lo);
            size_t o = dst_off + (size_t)s * D_K;
            *(uint32_t*)(dhi + o) = hi;
            *(uint32_t*)(dlo + o) = lo;
        }
    }
}

// ---------------- Flash attention (causal, HMMA bf16-split) ----------------
// 128 threads / 4 warps; 64 q-rows per block, warp handles 16 rows.
// smem: KH/KL/VH/VL 64x64 bf16 tiles (8KB each, 32KB total); Q staged via KH/KL.
#define KH 0
#define KL 8192
#define VH 16384
#define VL 24576

__global__ void __launch_bounds__(128) flash_kernel()
{
    __shared__ __align__(16) char fsm[32768];
    const uint32_t sb = smem_u32(fsm);

    const int qt = blockIdx.x;
    const int h  = blockIdx.y;
    const int bb = blockIdx.z;
    const int tid  = threadIdx.x;
    const int wid  = tid >> 5;
    const int lane = tid & 31;

    const size_t hoff = (size_t)(bb * NUM_HEADS + h) * SEQ * D_K;
    const __nv_bfloat16* Qh = g_qhi + hoff;
    const __nv_bfloat16* Ql = g_qlo + hoff;
    const __nv_bfloat16* Kh = g_khi + hoff;
    const __nv_bfloat16* Kl = g_klo + hoff;
    const __nv_bfloat16* Vh = g_vhi + hoff;
    const __nv_bfloat16* Vl = g_vlo + hoff;
    const int q0 = qt * 64;

    const int rA = (lane & 7) + 8 * ((lane >> 3) & 1);
    const int pA = (lane >> 4) & 1;

    // ---- stage Q tile through KH/KL, extract frags ----
    for (int i = tid; i < 512; i += 128) {
        int r = i >> 3, ch = i & 7;
        int sw = r * 128 + ((ch ^ (r & 7)) << 4);
        size_t gix = (size_t)(q0 + r) * D_K + ch * 8;
        *(uint4*)(fsm + KH + sw) = *(const uint4*)(Qh + gix);
        *(uint4*)(fsm + KL + sw) = *(const uint4*)(Ql + gix);
    }
    __syncthreads();

    uint32_t aq[4][4], aql[4][4];
#pragma unroll
    for (int ks = 0; ks < 4; ks++) {
        int slot = ks * 2 + pA;
        int row  = wid * 16 + rA;
        uint32_t ad = sb + KH + row * 128 + ((slot ^ (row & 7)) << 4);
        ldmx4(aq[ks], ad);
        ldmx4(aql[ks], ad + (KL - KH));
    }
    __syncthreads();  // Q frags extracted; KH/KL free for K tiles

    float out[8][4];
#pragma unroll
    for (int g = 0; g < 8; g++)
#pragma unroll
        for (int e = 0; e < 4; e++) out[g][e] = 0.f;
    float m0 = -1e30f, m1 = -1e30f, l0 = 0.f, l1 = 0.f;

    for (int kt = 0; kt <= qt; kt++) {
        // load K and V tiles (hi/lo) swizzled
        for (int i = tid; i < 512; i += 128) {
            int r = i >> 3, ch = i & 7;
            int sw = r * 128 + ((ch ^ (r & 7)) << 4);
            size_t gix = (size_t)(kt * 64 + r) * D_K + ch * 8;
            *(uint4*)(fsm + KH + sw) = *(const uint4*)(Kh + gix);
            *(uint4*)(fsm + KL + sw) = *(const uint4*)(Kl + gix);
            *(uint4*)(fsm + VH + sw) = *(const uint4*)(Vh + gix);
            *(uint4*)(fsm + VL + sw) = *(const uint4*)(Vl + gix);
        }
        __syncthreads();

        // ---- scores S = Q K^T (3-MMA split) ----
        float s[8][4];
#pragma unroll
        for (int g = 0; g < 8; g++)
#pragma unroll
            for (int e = 0; e < 4; e++) s[g][e] = 0.f;

#pragma unroll
        for (int ks = 0; ks < 4; ks++) {
            const int slot = ks * 2 + pA;
            uint32_t bh[8][2], bl[8][2];
#pragma unroll
            for (int g2 = 0; g2 < 4; g2++) {
                int row = g2 * 16 + rA;
                uint32_t bd = sb + KH + row * 128 + ((slot ^ (row & 7)) << 4);
                uint32_t t0[4], t1[4];
                ldmx4(t0, bd);
                ldmx4(t1, bd + (KL - KH));
                bh[g2 * 2 + 0][0] = t0[0]; bh[g2 * 2 + 0][1] = t0[2];
                bh[g2 * 2 + 1][0] = t0[1]; bh[g2 * 2 + 1][1] = t0[3];
                bl[g2 * 2 + 0][0] = t1[0]; bl[g2 * 2 + 0][1] = t1[2];
                bl[g2 * 2 + 1][0] = t1[1]; bl[g2 * 2 + 1][1] = t1[3];
            }
#pragma unroll
            for (int g = 0; g < 8; g++) {
                mma_bf16(s[g], aq[ks], bh[g]);
                mma_bf16(s[g], aq[ks], bl[g]);
                mma_bf16(s[g], aql[ks], bh[g]);
            }
        }

        // ---- causal mask on diagonal tile ----
        if (kt == qt) {
            int r0 = wid * 16 + (lane >> 2);
#pragma unroll
            for (int g = 0; g < 8; g++) {
                int cb = 8 * g + 2 * (lane & 3);
                if (cb     > r0)     s[g][0] = -1e30f;
                if (cb + 1 > r0)     s[g][1] = -1e30f;
                if (cb     > r0 + 8) s[g][2] = -1e30f;
                if (cb + 1 > r0 + 8) s[g][3] = -1e30f;
            }
        }

        // ---- online softmax (rows r0=lane>>2 and r0+8; quad reduce) ----
        float mx0 = -1e30f, mx1 = -1e30f;
#pragma unroll
        for (int g = 0; g < 8; g++) {
            mx0 = fmaxf(mx0, fmaxf(s[g][0], s[g][1]));
            mx1 = fmaxf(mx1, fmaxf(s[g][2], s[g][3]));
        }
        mx0 = fmaxf(mx0, __shfl_xor_sync(0xffffffffu, mx0, 1));
        mx0 = fmaxf(mx0, __shfl_xor_sync(0xffffffffu, mx0, 2));
        mx1 = fmaxf(mx1, __shfl_xor_sync(0xffffffffu, mx1, 1));
        mx1 = fmaxf(mx1, __shfl_xor_sync(0xffffffffu, mx1, 2));

        float mn0 = fmaxf(m0, mx0), mn1 = fmaxf(m1, mx1);
        float sf0 = __expf(m0 - mn0), sf1 = __expf(m1 - mn1);
        m0 = mn0; m1 = mn1;

        float rs0 = 0.f, rs1 = 0.f;
#pragma unroll
        for (int g = 0; g < 8; g++) {
            s[g][0] = __expf(s[g][0] - mn0);
            s[g][1] = __expf(s[g][1] - mn0);
            s[g][2] = __expf(s[g][2] - mn1);
            s[g][3] = __expf(s[g][3] - mn1);
            rs0 += s[g][0] + s[g][1];
            rs1 += s[g][2] + s[g][3];
        }
        rs0 += __shfl_xor_sync(0xffffffffu, rs0, 1);
        rs0 += __shfl_xor_sync(0xffffffffu, rs0, 2);
        rs1 += __shfl_xor_sync(0xffffffffu, rs1, 1);
        rs1 += __shfl_xor_sync(0xffffffffu, rs1, 2);
        l0 = l0 * sf0 + rs0;
        l1 = l1 * sf1 + rs1;
#pragma unroll
        for (int g = 0; g < 8; g++) {
            out[g][0] *= sf0; out[g][1] *= sf0;
            out[g][2] *= sf1; out[g][3] *= sf1;
        }

        // ---- P -> A-frags (hi/lo) in registers ----
        uint32_t ap[4][4], apl[4][4];
#pragma unroll
        for (int j = 0; j < 4; j++) {
            split2(s[2*j][0],   s[2*j][1],   ap[j][0], apl[j][0]);
            split2(s[2*j][2],   s[2*j][3],   ap[j][1], apl[j][1]);
            split2(s[2*j+1][0], s[2*j+1][1], ap[j][2], apl[j][2]);
            split2(s[2*j+1][2], s[2*j+1][3], ap[j][3], apl[j][3]);
        }

        // ---- O += P V (V via ldmatrix.trans, 3-MMA split) ----
#pragma unroll
        for (int j = 0; j < 4; j++) {
            uint32_t bv[8][2], bvl[8][2];
            int krow = j * 16 + (lane & 7) + 8 * ((lane >> 3) & 1);
            int colh = (lane >> 4) & 1;
#pragma unroll
            for (int dp = 0; dp < 4; dp++) {
                int slot = dp * 2 + colh;
                uint32_t ad = sb + VH + krow * 128 + ((slot ^ (krow & 7)) << 4);
                uint32_t t0[4], t1[4];
                ldmx4t(t0, ad);
                ldmx4t(t1, ad + (VL - VH));
                bv[dp * 2 + 0][0] = t0[0]; bv[dp * 2 + 0][1] = t0[1];
                bv[dp * 2 + 1][0] = t0[2]; bv[dp * 2 + 1][1] = t0[3];
                bvl[dp * 2 + 0][0] = t1[0]; bvl[dp * 2 + 0][1] = t1[1];
                bvl[dp * 2 + 1][0] = t1[2]; bvl[dp * 2 + 1][1] = t1[3];
            }
#pragma unroll
            for (int g = 0; g < 8; g++) {
                mma_bf16(out[g], ap[j], bv[g]);
                mma_bf16(out[g], ap[j], bvl[g]);
                mma_bf16(out[g], apl[j], bv[g]);
            }
        }
        __syncthreads();  // PV done reading smem before next tile load
    }

    // ---- epilogue: O/l, bf16 split, write g_ahi/g_alo [b,s,h*dk] ----
    float inv0 = 1.f / l0, inv1 = 1.f / l1;
    int srow = q0 + wid * 16 + (lane >> 2);
    size_t base0 = ((size_t)(bb * SEQ) + srow) * D_MODEL + h * 64;
    size_t base1 = base0 + (size_t)8 * D_MODEL;
#pragma unroll
    for (int g = 0; g < 8; g++) {
        int d = 8 * g + 2 * (lane & 3);
        uint32_t hi, lo;
        split2(out[g][0] * inv0, out[g][1] * inv0, hi, lo);
        *(uint32_t*)(g_ahi + base0 + d) = hi;
        *(uint32_t*)(g_alo + base0 + d) = lo;
        split2(out[g][2] * inv1, out[g][3] * inv1, hi, lo);
        *(uint32_t*)(g_ahi + base1 + d) = hi;
        *(uint32_t*)(g_alo + base1 + d) = lo;
    }
}

// ---------------- launch ----------------
extern "C" void kernel_launch(void* const* d_in, const int* in_sizes, int n_in,
                              void* d_out, int out_size)
{
    const float* x   = (const float*)d_in[0];
    const int*   pos = (const int*)  d_in[1];
    const float* wq  = (const float*)d_in[2];
    const float* wk  = (const float*)d_in[3];
    const float* wv  = (const float*)d_in[4];
    const float* wo  = (const float*)d_in[5];
    float* out = (float*)d_out;

    (void)in_sizes; (void)n_in; (void)out_size;

    static bool attr_done = false;
    if (!attr_done) {
        cudaFuncSetAttribute(qkv_mma_kernel, cudaFuncAttributeMaxDynamicSharedMemorySize,
                             GEMM_SMEM);
        cudaFuncSetAttribute(out_mma_kernel, cudaFuncAttributeMaxDynamicSharedMemorySize,
                             GEMM_SMEM);
        attr_done = true;
    }

    __nv_bfloat16 *xhi, *xlo, *whi0, *wlo0;
    cudaGetSymbolAddress((void**)&xhi,  g_xhi);
    cudaGetSymbolAddress((void**)&xlo,  g_xlo);
    cudaGetSymbolAddress((void**)&whi0, g_whi);
    cudaGetSymbolAddress((void**)&wlo0, g_wlo);

    const int n4x = M_TOK * D_MODEL / 4;
    const int n4w = D_MODEL * D_MODEL / 4;
    const size_t wsz = (size_t)D_MODEL * D_MODEL;

    // 0) conversions
    cvt_split_kernel<<<(n4x + 255) / 256, 256>>>((const float4*)x, xhi, xlo, n4x);
    cvt_split_kernel<<<(n4w + 255) / 256, 256>>>((const float4*)wq, whi0, wlo0, n4w);
    cvt_split_kernel<<<(n4w + 255) / 256, 256>>>((const float4*)wk, whi0 + wsz, wlo0 + wsz, n4w);
    cvt_split_kernel<<<(n4w + 255) / 256, 256>>>((const float4*)wv, whi0 + 2 * wsz, wlo0 + 2 * wsz, n4w);
    cvt_split_kernel<<<(n4w + 255) / 256, 256>>>((const float4*)wo, whi0 + 3 * wsz, wlo0 + 3 * wsz, n4w);

    // 1) QKV projections (HMMA)
    qkv_mma_kernel<<<dim3(D_MODEL / 128, M_TOK / 128, 3), 256, GEMM_SMEM>>>();

    // 2) RoPE + reshape + bf16 split
    rope_kernel<<<dim3(256, 1, 3), 256>>>(pos);

    // 3) flash attention (HMMA)
    flash_kernel<<<dim3(SEQ / 64, NUM_HEADS, BATCH), 128>>>();

    // 4) output projection (HMMA)
    out_mma_kernel<<<dim3(D_MODEL / 128, M_TOK / 128, 1), 256, GEMM_SMEM>>>(out);
}

// round 7
// speedup vs baseline: 2.6648x; 1.1182x over previous
#include <cuda_runtime.h>
#include <cuda_bf16.h>
#include <math.h>
#include <stdint.h>

#define D_MODEL   1024
#define NUM_HEADS 16
#define D_K       64
#define SEQ       2048
#define BATCH     2
#define M_TOK     (BATCH*SEQ)   // 4096

// ---------------- scratch (no allocation allowed) ----------------
__device__ float g_lin[3][(size_t)M_TOK * D_MODEL];                 // QKV linear outputs (fp32)

// bf16-split operands
__device__ __nv_bfloat16 g_xhi[(size_t)M_TOK * D_MODEL];
__device__ __nv_bfloat16 g_xlo[(size_t)M_TOK * D_MODEL];
__device__ __nv_bfloat16 g_whi[4][(size_t)D_MODEL * D_MODEL];
__device__ __nv_bfloat16 g_wlo[4][(size_t)D_MODEL * D_MODEL];
__device__ __nv_bfloat16 g_ahi[(size_t)M_TOK * D_MODEL];            // attn out hi
__device__ __nv_bfloat16 g_alo[(size_t)M_TOK * D_MODEL];            // attn out lo

// roped Q/K and V, bf16 hi/lo, [b,h,s,dk]
#define HSZ ((size_t)BATCH * NUM_HEADS * SEQ * D_K)
__device__ __nv_bfloat16 g_qhi[HSZ], g_qlo[HSZ];
__device__ __nv_bfloat16 g_khi[HSZ], g_klo[HSZ];
__device__ __nv_bfloat16 g_vhi[HSZ], g_vlo[HSZ];

// ---------------- helpers ----------------
__device__ __forceinline__ uint32_t smem_u32(const void* p) {
    uint32_t a;
    asm("{ .reg .u64 t; cvta.to.shared.u64 t, %1; cvt.u32.u64 %0, t; }" : "=r"(a) : "l"(p));
    return a;
}

__device__ __forceinline__ void cp_async16(uint32_t dst, const void* src) {
    asm volatile("cp.async.cg.shared.global [%0], [%1], 16;" :: "r"(dst), "l"(src));
}
#define CP_COMMIT() asm volatile("cp.async.commit_group;" ::: "memory")
#define CP_WAIT(n)  asm volatile("cp.async.wait_group %0;" :: "n"(n) : "memory")

__device__ __forceinline__ void ldmx4(uint32_t* r, uint32_t addr) {
    asm volatile("ldmatrix.sync.aligned.m8n8.x4.shared.b16 {%0,%1,%2,%3}, [%4];"
                 : "=r"(r[0]), "=r"(r[1]), "=r"(r[2]), "=r"(r[3]) : "r"(addr));
}

__device__ __forceinline__ void ldmx4t(uint32_t* r, uint32_t addr) {
    asm volatile("ldmatrix.sync.aligned.m8n8.x4.trans.shared.b16 {%0,%1,%2,%3}, [%4];"
                 : "=r"(r[0]), "=r"(r[1]), "=r"(r[2]), "=r"(r[3]) : "r"(addr));
}

__device__ __forceinline__ void mma_bf16(float* d, const uint32_t* a, const uint32_t* b) {
    asm volatile("mma.sync.aligned.m16n8k16.row.col.f32.bf16.bf16.f32 "
                 "{%0,%1,%2,%3}, {%4,%5,%6,%7}, {%8,%9}, {%0,%1,%2,%3};"
                 : "+f"(d[0]), "+f"(d[1]), "+f"(d[2]), "+f"(d[3])
                 : "r"(a[0]), "r"(a[1]), "r"(a[2]), "r"(a[3]), "r"(b[0]), "r"(b[1]));
}

__device__ __forceinline__ void split2(float a, float b, uint32_t& hi, uint32_t& lo) {
    __nv_bfloat162 h = __floats2bfloat162_rn(a, b);
    float ra = a - __bfloat162float(h.x);
    float rb = b - __bfloat162float(h.y);
    __nv_bfloat162 l = __floats2bfloat162_rn(ra, rb);
    hi = *(uint32_t*)&h;
    lo = *(uint32_t*)&l;
}

// ---------------- split conversion: fp32 -> (bf16 hi, bf16 lo) ----------------
__global__ void cvt_split_kernel(const float4* __restrict__ src,
                                 __nv_bfloat16* __restrict__ hi,
                                 __nv_bfloat16* __restrict__ lo, int n4)
{
    int i = blockIdx.x * blockDim.x + threadIdx.x;
    if (i >= n4) return;
    float4 v = src[i];
    __nv_bfloat16 h[4], l[4];
    float f[4] = {v.x, v.y, v.z, v.w};
#pragma unroll
    for (int j = 0; j < 4; j++) {
        h[j] = __float2bfloat16(f[j]);
        l[j] = __float2bfloat16(f[j] - __bfloat162float(h[j]));
    }
    *(uint2*)&hi[(size_t)i * 4] = *(uint2*)h;
    *(uint2*)&lo[(size_t)i * 4] = *(uint2*)l;
}

// ---------------- HMMA GEMM: C[M,N] = A[M,K] * W[N,K]^T (bf16 split, 3 MMAs) --------
// 128x128 tile, BK=64, 8 warps as 2(M)x4(N); cp.async tile loads.
#define GEMM_SMEM (4 * 128 * 64 * 2)

__device__ __forceinline__ void mma_gemm_body(const __nv_bfloat16* __restrict__ Ahi,
                                              const __nv_bfloat16* __restrict__ Alo,
                                              const __nv_bfloat16* __restrict__ Whi,
                                              const __nv_bfloat16* __restrict__ Wlo,
                                              float* __restrict__ C)
{
    extern __shared__ char smem[];
    const uint32_t sb = smem_u32(smem);
    const int K = D_MODEL, N = D_MODEL;
    const int bm = blockIdx.y * 128;
    const int bn = blockIdx.x * 128;
    const int tid  = threadIdx.x;
    const int wid  = tid >> 5;
    const int lane = tid & 31;
    const int wm = (wid >> 2) * 64;
    const int wn = (wid & 3) * 32;

    const __nv_bfloat16* srcs[4] = {
        Ahi + (size_t)bm * K, Alo + (size_t)bm * K,
        Whi + (size_t)bn * K, Wlo + (size_t)bn * K };

    float acc[4][4][4];
#pragma unroll
    for (int i = 0; i < 4; i++)
#pragma unroll
        for (int j = 0; j < 4; j++)
#pragma unroll
            for (int e = 0; e < 4; e++) acc[i][j][e] = 0.f;

    const int rA = (lane & 7) + ((lane >> 3) & 1) * 8;
    const int pA = (lane >> 4) & 1;

    for (int c = 0; c < 16; ++c) {
        const int k0 = c * 64;
        __syncthreads();   // all ldmatrix reads of previous chunk done
#pragma unroll
        for (int t = 0; t < 4; t++) {
            const __nv_bfloat16* S = srcs[t];
#pragma unroll
            for (int i = tid; i < 1024; i += 256) {
                int row = i >> 3, slot = i & 7;
                cp_async16(sb + t * 16384 + row * 128 + ((slot ^ (row & 7)) << 4),
                           S + (size_t)row * K + k0 + slot * 8);
            }
        }
        CP_COMMIT();
        CP_WAIT(0);
        __syncthreads();

#pragma unroll
        for (int kk = 0; kk < 4; kk++) {
            const int slot = kk * 2 + pA;
            uint32_t ah[4][4], al[4][4], bh[4][2], bl[4][2];
#pragma unroll
            for (int im = 0; im < 4; im++) {
                int row = wm + im * 16 + rA;
                uint32_t ad = sb + row * 128 + ((slot ^ (row & 7)) << 4);
                ldmx4(ah[im], ad);
                ldmx4(al[im], ad + 16384);
            }
#pragma unroll
            for (int g = 0; g < 2; g++) {
                int row = wn + g * 16 + rA;
                uint32_t bd = sb + 32768 + row * 128 + ((slot ^ (row & 7)) << 4);
                uint32_t t0[4], t1[4];
                ldmx4(t0, bd);
                ldmx4(t1, bd + 16384);
                bh[g * 2 + 0][0] = t0[0]; bh[g * 2 + 0][1] = t0[2];
                bh[g * 2 + 1][0] = t0[1]; bh[g * 2 + 1][1] = t0[3];
                bl[g * 2 + 0][0] = t1[0]; bl[g * 2 + 0][1] = t1[2];
                bl[g * 2 + 1][0] = t1[1]; bl[g * 2 + 1][1] = t1[3];
            }
#pragma unroll
            for (int im = 0; im < 4; im++)
#pragma unroll
                for (int jn = 0; jn < 4; jn++) {
                    mma_bf16(acc[im][jn], ah[im], bh[jn]);
                    mma_bf16(acc[im][jn], ah[im], bl[jn]);
                    mma_bf16(acc[im][jn], al[im], bh[jn]);
                }
        }
    }

    const int r0 = bm + wm + (lane >> 2);
    const int c0 = bn + wn + (lane & 3) * 2;
#pragma unroll
    for (int im = 0; im < 4; im++)
#pragma unroll
        for (int jn = 0; jn < 4; jn++) {
            float* p0 = C + (size_t)(r0 + im * 16) * N + c0 + jn * 8;
            float* p1 = C + (size_t)(r0 + im * 16 + 8) * N + c0 + jn * 8;
            *(float2*)p0 = make_float2(acc[im][jn][0], acc[im][jn][1]);
            *(float2*)p1 = make_float2(acc[im][jn][2], acc[im][jn][3]);
        }
}

__global__ void __launch_bounds__(256) qkv_mma_kernel()
{
    const int z = blockIdx.z;
    mma_gemm_body(g_xhi, g_xlo, &g_whi[z][0], &g_wlo[z][0], &g_lin[z][0]);
}

__global__ void __launch_bounds__(256) out_mma_kernel(float* __restrict__ out)
{
    mma_gemm_body(g_ahi, g_alo, &g_whi[3][0], &g_wlo[3][0], out);
}

// ---------------- RoPE + reshape to [b,h,s,dk], bf16 hi/lo output ----------------
__global__ void rope_kernel(const int* __restrict__ pos)
{
    const int z   = blockIdx.z;                         // 0=Q (rope+scale), 1=K (rope), 2=V (copy)
    const int idx = blockIdx.x * blockDim.x + threadIdx.x;
    const int j     = idx & 31;
    const int h     = (idx >> 5) & 15;
    const int chunk = (idx >> 9) & 63;
    const int b     = (idx >> 15) & 1;

    const float* src_base = &g_lin[z][0] + ((size_t)b * SEQ) * D_MODEL + h * 64 + 2 * j;
    __nv_bfloat16* dhi = (z == 0) ? g_qhi : (z == 1) ? g_khi : g_vhi;
    __nv_bfloat16* dlo = (z == 0) ? g_qlo : (z == 1) ? g_klo : g_vlo;
    const size_t dst_off = ((size_t)(b * NUM_HEADS + h) * SEQ) * D_K + 2 * j;
    const int s0 = chunk * 32;

    if (z == 2) {
        for (int ss = 0; ss < 32; ss++) {
            int s = s0 + ss;
            const float* sp = src_base + (size_t)s * D_MODEL;
            uint32_t hi, lo;
            split2(sp[0], sp[1], hi, lo);
            size_t o = dst_off + (size_t)s * D_K;
            *(uint32_t*)(dhi + o) = hi;
            *(uint32_t*)(dlo + o) = lo;
        }
    } else {
        const double freq   = exp((double)j * -0.28782313662425575);
        const double inv2pi = 0.15915494309189535;
        const double twopi  = 6.283185307179586;
        const float qscale = (z == 0) ? 0.125f : 1.0f;
        for (int ss = 0; ss < 32; ss++) {
            int s = s0 + ss;
            double ang = (double)pos[s] * freq;
            ang -= trunc(ang * inv2pi) * twopi;
            float c, sn;
            sincosf((float)ang, &sn, &c);
            const float* sp = src_base + (size_t)s * D_MODEL;
            float x1 = sp[0], x2 = sp[1];
            float r1 = (x1 * c - x2 * sn) * qscale;
            float r2 = (x1 * sn + x2 * c) * qscale;
            uint32_t hi, lo;
            split2(r1, r2, hi, lo);
            size_t o = dst_off + (size_t)s * D_K;
            *(uint32_t*)(dhi + o) = hi;
            *(uint32_t*)(dlo + o) = lo;
        }
    }
}

// ---------------- Flash attention (causal, HMMA bf16-split, 2-stage cp.async) --------
// 128 threads / 4 warps; 64 q-rows per block.
// Dynamic smem: 2 stages x 32KB; per stage: KH/KL/VH/VL 64x64 bf16 tiles (8KB each).
#define KH 0
#define KL 8192
#define VH 16384
#define VL 24576
#define FLASH_SMEM 65536

__global__ void __launch_bounds__(128) flash_kernel()
{
    extern __shared__ __align__(16) char fsm[];
    const uint32_t sb = smem_u32(fsm);

    const int qt = blockIdx.x;
    const int h  = blockIdx.y;
    const int bb = blockIdx.z;
    const int tid  = threadIdx.x;
    const int wid  = tid >> 5;
    const int lane = tid & 31;

    const size_t hoff = (size_t)(bb * NUM_HEADS + h) * SEQ * D_K;
    const __nv_bfloat16* Qh = g_qhi + hoff;
    const __nv_bfloat16* Ql = g_qlo + hoff;
    const __nv_bfloat16* Kh = g_khi + hoff;
    const __nv_bfloat16* Kl = g_klo + hoff;
    const __nv_bfloat16* Vh = g_vhi + hoff;
    const __nv_bfloat16* Vl = g_vlo + hoff;
    const int q0 = qt * 64;

    const int rA = (lane & 7) + 8 * ((lane >> 3) & 1);
    const int pA = (lane >> 4) & 1;

    // group 0: Q tile -> stage1 KH/KL slots
    for (int i = tid; i < 512; i += 128) {
        int r = i >> 3, ch = i & 7;
        int sw = r * 128 + ((ch ^ (r & 7)) << 4);
        size_t gix = (size_t)(q0 + r) * D_K + ch * 8;
        cp_async16(sb + 32768 + KH + sw, Qh + gix);
        cp_async16(sb + 32768 + KL + sw, Ql + gix);
    }
    CP_COMMIT();
    // group 1: kt=0 K/V tiles -> stage0
    for (int i = tid; i < 512; i += 128) {
        int r = i >> 3, ch = i & 7;
        int sw = r * 128 + ((ch ^ (r & 7)) << 4);
        size_t gix = (size_t)r * D_K + ch * 8;
        cp_async16(sb + KH + sw, Kh + gix);
        cp_async16(sb + KL + sw, Kl + gix);
        cp_async16(sb + VH + sw, Vh + gix);
        cp_async16(sb + VL + sw, Vl + gix);
    }
    CP_COMMIT();

    CP_WAIT(1);        // Q ready (kt=0 may still be in flight)
    __syncthreads();

    uint32_t aq[4][4], aql[4][4];
#pragma unroll
    for (int ks = 0; ks < 4; ks++) {
        int slot = ks * 2 + pA;
        int row  = wid * 16 + rA;
        uint32_t ad = sb + 32768 + KH + row * 128 + ((slot ^ (row & 7)) << 4);
        ldmx4(aq[ks], ad);
        ldmx4(aql[ks], ad + (KL - KH));
    }

    float out[8][4];
#pragma unroll
    for (int g = 0; g < 8; g++)
#pragma unroll
        for (int e = 0; e < 4; e++) out[g][e] = 0.f;
    float m0 = -1e30f, m1 = -1e30f, l0 = 0.f, l1 = 0.f;

    for (int kt = 0; kt <= qt; kt++) {
        const uint32_t sbs = sb + (uint32_t)(kt & 1) * 32768;
        CP_WAIT(0);        // tile kt resident
        __syncthreads();   // all warps past previous compute (incl. Q frag extraction)

        // prefetch kt+1 into the other stage (overlaps the MMAs below)
        if (kt < qt) {
            const uint32_t sbn = sb + (uint32_t)((kt + 1) & 1) * 32768;
            for (int i = tid; i < 512; i += 128) {
                int r = i >> 3, ch = i & 7;
                int sw = r * 128 + ((ch ^ (r & 7)) << 4);
                size_t gix = (size_t)((kt + 1) * 64 + r) * D_K + ch * 8;
                cp_async16(sbn + KH + sw, Kh + gix);
                cp_async16(sbn + KL + sw, Kl + gix);
                cp_async16(sbn + VH + sw, Vh + gix);
                cp_async16(sbn + VL + sw, Vl + gix);
            }
            CP_COMMIT();
        }

        // ---- scores S = Q K^T (3-MMA split) ----
        float s[8][4];
#pragma unroll
        for (int g = 0; g < 8; g++)
#pragma unroll
            for (int e = 0; e < 4; e++) s[g][e] = 0.f;

#pragma unroll
        for (int ks = 0; ks < 4; ks++) {
            const int slot = ks * 2 + pA;
            uint32_t bh[8][2], bl[8][2];
#pragma unroll
            for (int g2 = 0; g2 < 4; g2++) {
                int row = g2 * 16 + rA;
                uint32_t bd = sbs + KH + row * 128 + ((slot ^ (row & 7)) << 4);
                uint32_t t0[4], t1[4];
                ldmx4(t0, bd);
                ldmx4(t1, bd + (KL - KH));
                bh[g2 * 2 + 0][0] = t0[0]; bh[g2 * 2 + 0][1] = t0[2];
                bh[g2 * 2 + 1][0] = t0[1]; bh[g2 * 2 + 1][1] = t0[3];
                bl[g2 * 2 + 0][0] = t1[0]; bl[g2 * 2 + 0][1] = t1[2];
                bl[g2 * 2 + 1][0] = t1[1]; bl[g2 * 2 + 1][1] = t1[3];
            }
#pragma unroll
            for (int g = 0; g < 8; g++) {
                mma_bf16(s[g], aq[ks], bh[g]);
                mma_bf16(s[g], aq[ks], bl[g]);
                mma_bf16(s[g], aql[ks], bh[g]);
            }
        }

        // ---- causal mask on diagonal tile ----
        if (kt == qt) {
            int r0 = wid * 16 + (lane >> 2);
#pragma unroll
            for (int g = 0; g < 8; g++) {
                int cb = 8 * g + 2 * (lane & 3);
                if (cb     > r0)     s[g][0] = -1e30f;
                if (cb + 1 > r0)     s[g][1] = -1e30f;
                if (cb     > r0 + 8) s[g][2] = -1e30f;
                if (cb + 1 > r0 + 8) s[g][3] = -1e30f;
            }
        }

        // ---- online softmax ----
        float mx0 = -1e30f, mx1 = -1e30f;
#pragma unroll
        for (int g = 0; g < 8; g++) {
            mx0 = fmaxf(mx0, fmaxf(s[g][0], s[g][1]));
            mx1 = fmaxf(mx1, fmaxf(s[g][2], s[g][3]));
        }
        mx0 = fmaxf(mx0, __shfl_xor_sync(0xffffffffu, mx0, 1));
        mx0 = fmaxf(mx0, __shfl_xor_sync(0xffffffffu, mx0, 2));
        mx1 = fmaxf(mx1, __shfl_xor_sync(0xffffffffu, mx1, 1));
        mx1 = fmaxf(mx1, __shfl_xor_sync(0xffffffffu, mx1, 2));

        float mn0 = fmaxf(m0, mx0), mn1 = fmaxf(m1, mx1);
        float sf0 = __expf(m0 - mn0), sf1 = __expf(m1 - mn1);
        m0 = mn0; m1 = mn1;

        float rs0 = 0.f, rs1 = 0.f;
#pragma unroll
        for (int g = 0; g < 8; g++) {
            s[g][0] = __expf(s[g][0] - mn0);
            s[g][1] = __expf(s[g][1] - mn0);
            s[g][2] = __expf(s[g][2] - mn1);
            s[g][3] = __expf(s[g][3] - mn1);
            rs0 += s[g][0] + s[g][1];
            rs1 += s[g][2] + s[g][3];
        }
        rs0 += __shfl_xor_sync(0xffffffffu, rs0, 1);
        rs0 += __shfl_xor_sync(0xffffffffu, rs0, 2);
        rs1 += __shfl_xor_sync(0xffffffffu, rs1, 1);
        rs1 += __shfl_xor_sync(0xffffffffu, rs1, 2);
        l0 = l0 * sf0 + rs0;
        l1 = l1 * sf1 + rs1;
#pragma unroll
        for (int g = 0; g < 8; g++) {
            out[g][0] *= sf0; out[g][1] *= sf0;
            out[g][2] *= sf1; out[g][3] *= sf1;
        }

        // ---- P -> A-frags (hi/lo) in registers ----
        uint32_t ap[4][4], apl[4][4];
#pragma unroll
        for (int j = 0; j < 4; j++) {
            split2(s[2*j][0],   s[2*j][1],   ap[j][0], apl[j][0]);
            split2(s[2*j][2],   s[2*j][3],   ap[j][1], apl[j][1]);
            split2(s[2*j+1][0], s[2*j+1][1], ap[j][2], apl[j][2]);
            split2(s[2*j+1][2], s[2*j+1][3], ap[j][3], apl[j][3]);
        }

        // ---- O += P V (V via ldmatrix.trans, 3-MMA split) ----
#pragma unroll
        for (int j = 0; j < 4; j++) {
            uint32_t bv[8][2], bvl[8][2];
            int krow = j * 16 + (lane & 7) + 8 * ((lane >> 3) & 1);
            int colh = (lane >> 4) & 1;
#pragma unroll
            for (int dp = 0; dp < 4; dp++) {
                int slot = dp * 2 + colh;
                uint32_t ad = sbs + VH + krow * 128 + ((slot ^ (krow & 7)) << 4);
                uint32_t t0[4], t1[4];
                ldmx4t(t0, ad);
                ldmx4t(t1, ad + (VL - VH));
                bv[dp * 2 + 0][0] = t0[0]; bv[dp * 2 + 0][1] = t0[1];
                bv[dp * 2 + 1][0] = t0[2]; bv[dp * 2 + 1][1] = t0[3];
                bvl[dp * 2 + 0][0] = t1[0]; bvl[dp * 2 + 0][1] = t1[1];
                bvl[dp * 2 + 1][0] = t1[2]; bvl[dp * 2 + 1][1] = t1[3];
            }
#pragma unroll
            for (int g = 0; g < 8; g++) {
                mma_bf16(out[g], ap[j], bv[g]);
                mma_bf16(out[g], ap[j], bvl[g]);
                mma_bf16(out[g], apl[j], bv[g]);
            }
        }
        // no trailing sync: next iteration's CP_WAIT + __syncthreads protects the
        // write-after-read on the stage being refilled (issued only after that sync).
    }

    // ---- epilogue: O/l, bf16 split, write g_ahi/g_alo [b,s,h*dk] ----
    float inv0 = 1.f / l0, inv1 = 1.f / l1;
    int srow = q0 + wid * 16 + (lane >> 2);
    size_t base0 = ((size_t)(bb * SEQ) + srow) * D_MODEL + h * 64;
    size_t base1 = base0 + (size_t)8 * D_MODEL;
#pragma unroll
    for (int g = 0; g < 8; g++) {
        int d = 8 * g + 2 * (lane & 3);
        uint32_t hi, lo;
        split2(out[g][0] * inv0, out[g][1] * inv0, hi, lo);
        *(uint32_t*)(g_ahi + base0 + d) = hi;
        *(uint32_t*)(g_alo + base0 + d) = lo;
        split2(out[g][2] * inv1, out[g][3] * inv1, hi, lo);
        *(uint32_t*)(g_ahi + base1 + d) = hi;
        *(uint32_t*)(g_alo + base1 + d) = lo;
    }
}

// ---------------- launch ----------------
extern "C" void kernel_launch(void* const* d_in, const int* in_sizes, int n_in,
                              void* d_out, int out_size)
{
    const float* x   = (const float*)d_in[0];
    const int*   pos = (const int*)  d_in[1];
    const float* wq  = (const float*)d_in[2];
    const float* wk  = (const float*)d_in[3];
    const float* wv  = (const float*)d_in[4];
    const float* wo  = (const float*)d_in[5];
    float* out = (float*)d_out;

    (void)in_sizes; (void)n_in; (void)out_size;

    static bool attr_done = false;
    if (!attr_done) {
        cudaFuncSetAttribute(qkv_mma_kernel, cudaFuncAttributeMaxDynamicSharedMemorySize,
                             GEMM_SMEM);
        cudaFuncSetAttribute(out_mma_kernel, cudaFuncAttributeMaxDynamicSharedMemorySize,
                             GEMM_SMEM);
        cudaFuncSetAttribute(flash_kernel, cudaFuncAttributeMaxDynamicSharedMemorySize,
                             FLASH_SMEM);
        attr_done = true;
    }

    __nv_bfloat16 *xhi, *xlo, *whi0, *wlo0;
    cudaGetSymbolAddress((void**)&xhi,  g_xhi);
    cudaGetSymbolAddress((void**)&xlo,  g_xlo);
    cudaGetSymbolAddress((void**)&whi0, g_whi);
    cudaGetSymbolAddress((void**)&wlo0, g_wlo);

    const int n4x = M_TOK * D_MODEL / 4;
    const int n4w = D_MODEL * D_MODEL / 4;
    const size_t wsz = (size_t)D_MODEL * D_MODEL;

    // 0) conversions
    cvt_split_kernel<<<(n4x + 255) / 256, 256>>>((const float4*)x, xhi, xlo, n4x);
    cvt_split_kernel<<<(n4w + 255) / 256, 256>>>((const float4*)wq, whi0, wlo0, n4w);
    cvt_split_kernel<<<(n4w + 255) / 256, 256>>>((const float4*)wk, whi0 + wsz, wlo0 + wsz, n4w);
    cvt_split_kernel<<<(n4w + 255) / 256, 256>>>((const float4*)wv, whi0 + 2 * wsz, wlo0 + 2 * wsz, n4w);
    cvt_split_kernel<<<(n4w + 255) / 256, 256>>>((const float4*)wo, whi0 + 3 * wsz, wlo0 + 3 * wsz, n4w);

    // 1) QKV projections (HMMA)
    qkv_mma_kernel<<<dim3(D_MODEL / 128, M_TOK / 128, 3), 256, GEMM_SMEM>>>();

    // 2) RoPE + reshape + bf16 split
    rope_kernel<<<dim3(256, 1, 3), 256>>>(pos);

    // 3) flash attention (HMMA, 2-stage cp.async)
    flash_kernel<<<dim3(SEQ / 64, NUM_HEADS, BATCH), 128, FLASH_SMEM>>>();

    // 4) output projection (HMMA)
    out_mma_kernel<<<dim3(D_MODEL / 128, M_TOK / 128, 1), 256, GEMM_SMEM>>>(out);
}